// round 5
// baseline (speedup 1.0000x reference)
#include <cuda_runtime.h>
#include <math.h>

#define NUM_C 1000
#define DIMS  256
#define NMAX  262144
#define CAP   512      // per-class slot capacity (mean 262, sd ~16)
#define TILES 16       // ceil(1000/64)

// ---- device scratch ----
__device__ int   g_cursor[NUM_C];
__device__ int   g_idx[NUM_C * CAP];
__device__ float g_mn[NUM_C * DIMS];   // L2-normalized class means
__device__ int   g_maxkey;             // float-as-int key of (max_dot + 4.0f)

// ---------------------------------------------------------------------------
__global__ void init_k() {
    int i = blockIdx.x * blockDim.x + threadIdx.x;
    if (i < NUM_C) g_cursor[i] = i * CAP;
    if (i == 0)    g_maxkey = 0;   // encodes dot = -4.0
}

__global__ void scatter_k(const int* __restrict__ labels, int n) {
    int i = blockIdx.x * blockDim.x + threadIdx.x;
    if (i < n) {
        int lab = labels[i];
        int pos = atomicAdd(&g_cursor[lab], 1);
        g_idx[pos] = i;
    }
}

// One CTA per class. Thread t = (quad = t>>6, col4 = t&63): float4 column chunk,
// 8 rows in flight per thread (128B outstanding) for DRAM latency hiding.
__global__ void __launch_bounds__(256) gather_k(const float* __restrict__ f) {
    int c = blockIdx.x;
    int t = threadIdx.x;
    int beg = c * CAP;
    int cnt = g_cursor[c] - beg;
    int quad = t >> 6;
    int col  = t & 63;

    __shared__ int    sidx[256];
    __shared__ float4 sacc[256];
    __shared__ float  wsum[8];
    __shared__ float  sinv;

    const float4* f4 = (const float4*)f;   // row stride 64 float4
    float4 acc = make_float4(0.f, 0.f, 0.f, 0.f);

    for (int base = 0; base < cnt; base += 256) {
        int m = cnt - base; if (m > 256) m = 256;
        __syncthreads();
        if (t < m) sidx[t] = g_idx[beg + base + t];
        __syncthreads();
        int r = quad;
        for (; r + 28 < m; r += 32) {
            float4 v0 = f4[(long)sidx[r     ] * 64 + col];
            float4 v1 = f4[(long)sidx[r +  4] * 64 + col];
            float4 v2 = f4[(long)sidx[r +  8] * 64 + col];
            float4 v3 = f4[(long)sidx[r + 12] * 64 + col];
            float4 v4 = f4[(long)sidx[r + 16] * 64 + col];
            float4 v5 = f4[(long)sidx[r + 20] * 64 + col];
            float4 v6 = f4[(long)sidx[r + 24] * 64 + col];
            float4 v7 = f4[(long)sidx[r + 28] * 64 + col];
            acc.x += v0.x + v1.x + v2.x + v3.x + v4.x + v5.x + v6.x + v7.x;
            acc.y += v0.y + v1.y + v2.y + v3.y + v4.y + v5.y + v6.y + v7.y;
            acc.z += v0.z + v1.z + v2.z + v3.z + v4.z + v5.z + v6.z + v7.z;
            acc.w += v0.w + v1.w + v2.w + v3.w + v4.w + v5.w + v6.w + v7.w;
        }
        for (; r < m; r += 4) {
            float4 v = f4[(long)sidx[r] * 64 + col];
            acc.x += v.x; acc.y += v.y; acc.z += v.z; acc.w += v.w;
        }
    }

    sacc[t] = acc;
    __syncthreads();

    float4 mean = make_float4(0.f, 0.f, 0.f, 0.f);
    float ss = 0.f;
    if (t < 64) {
        float4 a = sacc[t], b = sacc[t + 64], c2 = sacc[t + 128], d = sacc[t + 192];
        float inv = 1.0f / (float)((cnt > 0) ? cnt : 1);
        mean.x = (a.x + b.x + c2.x + d.x) * inv;
        mean.y = (a.y + b.y + c2.y + d.y) * inv;
        mean.z = (a.z + b.z + c2.z + d.z) * inv;
        mean.w = (a.w + b.w + c2.w + d.w) * inv;
        ss = mean.x * mean.x + mean.y * mean.y + mean.z * mean.z + mean.w * mean.w;
    }
    #pragma unroll
    for (int o = 16; o > 0; o >>= 1) ss += __shfl_xor_sync(0xffffffffu, ss, o);
    if ((t & 31) == 0) wsum[t >> 5] = ss;
    __syncthreads();
    if (t == 0) {
        float tot = 0.f;
        #pragma unroll
        for (int w = 0; w < 8; w++) tot += wsum[w];
        sinv = (tot > 0.f) ? rsqrtf(tot) : 0.f;
    }
    __syncthreads();
    if (t < 64) {
        float s = sinv;
        float4 o4 = make_float4(mean.x * s, mean.y * s, mean.z * s, mean.w * s);
        ((float4*)g_mn)[(long)c * 64 + t] = o4;
    }
}

// Upper-triangular tiled gram-max. 64x64 tile, microtile rows {tx+16i} x cols {ty+16j}.
// SMEM: XOR-swizzled float4 chunks (conflict-free A, broadcast B).
// Double-buffered register prefetch: load k4+1 operands before consuming k4.
__global__ void __launch_bounds__(256, 1) gemmmax_k() {
    extern __shared__ float4 sm4[];
    float4* As = sm4;          // 64 rows * 64 chunks
    float4* Bs = sm4 + 64 * 64;

    int b = blockIdx.x;
    int ti = 0, rl = TILES;
    while (b >= rl) { b -= rl; ti++; rl--; }
    int tj = ti + b;

    int t = threadIdx.x;
    const float4* mn4 = (const float4*)g_mn;   // row stride 64 float4

    #pragma unroll
    for (int p = 0; p < 16; p++) {
        int idx = p * 256 + t;
        int r = idx >> 6;
        int kc = idx & 63;
        int rA = ti * 64 + r;
        int rB = tj * 64 + r;
        float4 va = (rA < NUM_C) ? mn4[(long)rA * 64 + kc] : make_float4(0.f,0.f,0.f,0.f);
        float4 vb = (rB < NUM_C) ? mn4[(long)rB * 64 + kc] : make_float4(0.f,0.f,0.f,0.f);
        int sw = kc ^ (r & 7);
        As[r * 64 + sw] = va;
        Bs[r * 64 + sw] = vb;
    }
    __syncthreads();

    int tx = t & 15, ty = t >> 4;
    int sa = tx & 7, sb = ty & 7;
    float cc[4][4];
    #pragma unroll
    for (int i = 0; i < 4; i++)
        #pragma unroll
        for (int j = 0; j < 4; j++) cc[i][j] = 0.f;

    float4 av[2][4], bv[2][4];
    // prologue: load k4 = 0
    {
        int ka = 0 ^ sa, kb = 0 ^ sb;
        #pragma unroll
        for (int i = 0; i < 4; i++) {
            av[0][i] = As[(tx + 16 * i) * 64 + ka];
            bv[0][i] = Bs[(ty + 16 * i) * 64 + kb];
        }
    }
    #pragma unroll
    for (int k4 = 0; k4 < 64; k4++) {
        int cur = k4 & 1, nxt = cur ^ 1;
        if (k4 < 63) {
            int ka = (k4 + 1) ^ sa, kb = (k4 + 1) ^ sb;
            #pragma unroll
            for (int i = 0; i < 4; i++) {
                av[nxt][i] = As[(tx + 16 * i) * 64 + ka];
                bv[nxt][i] = Bs[(ty + 16 * i) * 64 + kb];
            }
        }
        #pragma unroll
        for (int i = 0; i < 4; i++)
            #pragma unroll
            for (int j = 0; j < 4; j++) {
                cc[i][j] += av[cur][i].x * bv[cur][j].x;
                cc[i][j] += av[cur][i].y * bv[cur][j].y;
                cc[i][j] += av[cur][i].z * bv[cur][j].z;
                cc[i][j] += av[cur][i].w * bv[cur][j].w;
            }
    }

    // strict upper triangle only
    float lm = -4.0f;
    #pragma unroll
    for (int i = 0; i < 4; i++) {
        int gi = ti * 64 + tx + 16 * i;
        #pragma unroll
        for (int j = 0; j < 4; j++) {
            int gj = tj * 64 + ty + 16 * j;
            if (gi < gj && gj < NUM_C) lm = fmaxf(lm, cc[i][j]);
        }
    }
    #pragma unroll
    for (int o = 16; o > 0; o >>= 1) lm = fmaxf(lm, __shfl_xor_sync(0xffffffffu, lm, o));
    __shared__ float wm[8];
    if ((t & 31) == 0) wm[t >> 5] = lm;
    __syncthreads();
    if (t == 0) {
        float m = wm[0];
        #pragma unroll
        for (int w = 1; w < 8; w++) m = fmaxf(m, wm[w]);
        atomicMax(&g_maxkey, __float_as_int(m + 4.0f));
    }
}

__global__ void final_k(float* out, int n) {
    float maxd = __int_as_float(g_maxkey) - 4.0f;
    maxd = fminf(fmaxf(maxd, -1.f), 1.f);
    float mind = 1.0f - maxd;
    float loss = logf(1.0f / (mind + 1e-6f) + 1.0f);
    for (int i = threadIdx.x; i < n; i += blockDim.x) out[i] = loss;
}

// ---------------------------------------------------------------------------
extern "C" void kernel_launch(void* const* d_in, const int* in_sizes, int n_in,
                              void* d_out, int out_size) {
    const float* features = (const float*)d_in[0];
    const int*   labels   = (const int*)d_in[1];
    int n = in_sizes[1];

    const int smem_gemm = 2 * 64 * 64 * (int)sizeof(float4); // 131072 B
    cudaFuncSetAttribute(gemmmax_k, cudaFuncAttributeMaxDynamicSharedMemorySize, smem_gemm);

    init_k<<<4, 256>>>();
    scatter_k<<<(n + 255) / 256, 256>>>(labels, n);
    gather_k<<<NUM_C, 256>>>(features);
    gemmmax_k<<<TILES * (TILES + 1) / 2, 256, smem_gemm>>>();
    final_k<<<1, 256>>>((float*)d_out, out_size);
}

// round 6
// speedup vs baseline: 1.1000x; 1.1000x over previous
#include <cuda_runtime.h>
#include <math.h>

#define NUM_C 1000
#define DIMS  256
#define NMAX  262144
#define CAP   512      // per-class slot capacity (mean 262, sd ~16)
#define TILES 16       // ceil(1000/64)

// ---- device scratch ----
__device__ int   g_cursor[NUM_C];
__device__ int   g_idx[NUM_C * CAP];
__device__ float g_mn[NUM_C * DIMS];   // L2-normalized class means
__device__ int   g_maxkey;             // float-as-int key of (max_dot + 4.0f)

// ---------------------------------------------------------------------------
__global__ void init_k() {
    int i = blockIdx.x * blockDim.x + threadIdx.x;
    if (i < NUM_C) g_cursor[i] = i * CAP;
    if (i == 0)    g_maxkey = 0;   // encodes dot = -4.0
}

__global__ void scatter_k(const int* __restrict__ labels, int n) {
    int i = blockIdx.x * blockDim.x + threadIdx.x;
    if (i < n) {
        int lab = labels[i];
        int pos = atomicAdd(&g_cursor[lab], 1);
        g_idx[pos] = i;
    }
}

// One CTA per class. Thread t = (quad = t>>6, col4 = t&63): float4 column chunk,
// 4 rows in flight across quads, 4-deep unroll -> 64B outstanding per thread. (R4-proven)
__global__ void __launch_bounds__(256) gather_k(const float* __restrict__ f) {
    int c = blockIdx.x;
    int t = threadIdx.x;
    int beg = c * CAP;
    int cnt = g_cursor[c] - beg;
    int quad = t >> 6;
    int col  = t & 63;

    __shared__ int    sidx[256];
    __shared__ float4 sacc[256];
    __shared__ float  wsum[8];
    __shared__ float  sinv;

    const float4* f4 = (const float4*)f;   // row stride 64 float4
    float4 acc = make_float4(0.f, 0.f, 0.f, 0.f);

    for (int base = 0; base < cnt; base += 256) {
        int m = cnt - base; if (m > 256) m = 256;
        __syncthreads();
        if (t < m) sidx[t] = g_idx[beg + base + t];
        __syncthreads();
        int r = quad;
        for (; r + 12 < m; r += 16) {
            float4 v0 = f4[(long)sidx[r     ] * 64 + col];
            float4 v1 = f4[(long)sidx[r +  4] * 64 + col];
            float4 v2 = f4[(long)sidx[r +  8] * 64 + col];
            float4 v3 = f4[(long)sidx[r + 12] * 64 + col];
            acc.x += v0.x + v1.x + v2.x + v3.x;
            acc.y += v0.y + v1.y + v2.y + v3.y;
            acc.z += v0.z + v1.z + v2.z + v3.z;
            acc.w += v0.w + v1.w + v2.w + v3.w;
        }
        for (; r < m; r += 4) {
            float4 v = f4[(long)sidx[r] * 64 + col];
            acc.x += v.x; acc.y += v.y; acc.z += v.z; acc.w += v.w;
        }
    }

    sacc[t] = acc;
    __syncthreads();

    float4 mean = make_float4(0.f, 0.f, 0.f, 0.f);
    float ss = 0.f;
    if (t < 64) {
        float4 a = sacc[t], b = sacc[t + 64], c2 = sacc[t + 128], d = sacc[t + 192];
        float inv = 1.0f / (float)((cnt > 0) ? cnt : 1);
        mean.x = (a.x + b.x + c2.x + d.x) * inv;
        mean.y = (a.y + b.y + c2.y + d.y) * inv;
        mean.z = (a.z + b.z + c2.z + d.z) * inv;
        mean.w = (a.w + b.w + c2.w + d.w) * inv;
        ss = mean.x * mean.x + mean.y * mean.y + mean.z * mean.z + mean.w * mean.w;
    }
    #pragma unroll
    for (int o = 16; o > 0; o >>= 1) ss += __shfl_xor_sync(0xffffffffu, ss, o);
    if ((t & 31) == 0) wsum[t >> 5] = ss;
    __syncthreads();
    if (t == 0) {
        float tot = 0.f;
        #pragma unroll
        for (int w = 0; w < 8; w++) tot += wsum[w];
        sinv = (tot > 0.f) ? rsqrtf(tot) : 0.f;
    }
    __syncthreads();
    if (t < 64) {
        float s = sinv;
        float4 o4 = make_float4(mean.x * s, mean.y * s, mean.z * s, mean.w * s);
        ((float4*)g_mn)[(long)c * 64 + t] = o4;
    }
}

// Upper-triangular tiled gram-max (R4 structure). 64x64 tile, microtile
// rows {tx+16i} x cols {ty+16j}. XOR-swizzled smem (conflict-free A, broadcast B).
// Change vs R4: unroll 8 + 1-CTA launch bounds so ptxas pipelines loads itself.
__global__ void __launch_bounds__(256, 1) gemmmax_k() {
    extern __shared__ float4 sm4[];
    float4* As = sm4;          // 64 rows * 64 chunks
    float4* Bs = sm4 + 64 * 64;

    int b = blockIdx.x;
    int ti = 0, rl = TILES;
    while (b >= rl) { b -= rl; ti++; rl--; }
    int tj = ti + b;

    int t = threadIdx.x;
    const float4* mn4 = (const float4*)g_mn;   // row stride 64 float4

    #pragma unroll
    for (int p = 0; p < 16; p++) {
        int idx = p * 256 + t;
        int r = idx >> 6;
        int kc = idx & 63;
        int rA = ti * 64 + r;
        int rB = tj * 64 + r;
        float4 va = (rA < NUM_C) ? mn4[(long)rA * 64 + kc] : make_float4(0.f,0.f,0.f,0.f);
        float4 vb = (rB < NUM_C) ? mn4[(long)rB * 64 + kc] : make_float4(0.f,0.f,0.f,0.f);
        int sw = kc ^ (r & 7);
        As[r * 64 + sw] = va;
        Bs[r * 64 + sw] = vb;
    }
    __syncthreads();

    int tx = t & 15, ty = t >> 4;
    int sa = tx & 7, sb = ty & 7;
    float cc[4][4];
    #pragma unroll
    for (int i = 0; i < 4; i++)
        #pragma unroll
        for (int j = 0; j < 4; j++) cc[i][j] = 0.f;

    #pragma unroll 8
    for (int k4 = 0; k4 < 64; k4++) {
        int ka = k4 ^ sa;
        int kb = k4 ^ sb;
        float4 a0 = As[(tx     ) * 64 + ka];
        float4 a1 = As[(tx + 16) * 64 + ka];
        float4 a2 = As[(tx + 32) * 64 + ka];
        float4 a3 = As[(tx + 48) * 64 + ka];
        float4 b0 = Bs[(ty     ) * 64 + kb];
        float4 b1 = Bs[(ty + 16) * 64 + kb];
        float4 b2 = Bs[(ty + 32) * 64 + kb];
        float4 b3 = Bs[(ty + 48) * 64 + kb];
        float4 av[4] = {a0, a1, a2, a3};
        float4 bv[4] = {b0, b1, b2, b3};
        #pragma unroll
        for (int i = 0; i < 4; i++)
            #pragma unroll
            for (int j = 0; j < 4; j++) {
                cc[i][j] += av[i].x * bv[j].x;
                cc[i][j] += av[i].y * bv[j].y;
                cc[i][j] += av[i].z * bv[j].z;
                cc[i][j] += av[i].w * bv[j].w;
            }
    }

    // strict upper triangle only
    float lm = -4.0f;
    #pragma unroll
    for (int i = 0; i < 4; i++) {
        int gi = ti * 64 + tx + 16 * i;
        #pragma unroll
        for (int j = 0; j < 4; j++) {
            int gj = tj * 64 + ty + 16 * j;
            if (gi < gj && gj < NUM_C) lm = fmaxf(lm, cc[i][j]);
        }
    }
    #pragma unroll
    for (int o = 16; o > 0; o >>= 1) lm = fmaxf(lm, __shfl_xor_sync(0xffffffffu, lm, o));
    __shared__ float wm[8];
    if ((t & 31) == 0) wm[t >> 5] = lm;
    __syncthreads();
    if (t == 0) {
        float m = wm[0];
        #pragma unroll
        for (int w = 1; w < 8; w++) m = fmaxf(m, wm[w]);
        atomicMax(&g_maxkey, __float_as_int(m + 4.0f));
    }
}

__global__ void final_k(float* out, int n) {
    float maxd = __int_as_float(g_maxkey) - 4.0f;
    maxd = fminf(fmaxf(maxd, -1.f), 1.f);
    float mind = 1.0f - maxd;
    float loss = logf(1.0f / (mind + 1e-6f) + 1.0f);
    for (int i = threadIdx.x; i < n; i += blockDim.x) out[i] = loss;
}

// ---------------------------------------------------------------------------
extern "C" void kernel_launch(void* const* d_in, const int* in_sizes, int n_in,
                              void* d_out, int out_size) {
    const float* features = (const float*)d_in[0];
    const int*   labels   = (const int*)d_in[1];
    int n = in_sizes[1];

    const int smem_gemm = 2 * 64 * 64 * (int)sizeof(float4); // 131072 B
    cudaFuncSetAttribute(gemmmax_k, cudaFuncAttributeMaxDynamicSharedMemorySize, smem_gemm);

    init_k<<<4, 256>>>();
    scatter_k<<<(n + 255) / 256, 256>>>(labels, n);
    gather_k<<<NUM_C, 256>>>(features);
    gemmmax_k<<<TILES * (TILES + 1) / 2, 256, smem_gemm>>>();
    final_k<<<1, 256>>>((float*)d_out, out_size);
}